// round 13
// baseline (speedup 1.0000x reference)
#include <cuda_runtime.h>
#include <cstdint>

// ----------------------------------------------------------------------------
// ResBlock_71021579207010 — GB300 (sm_103a) — fused single kernel, v4.
//
// Math: ste_sign(relu(.)) == +1 -> conv1/bn1 dead; conv2 output is a
// per-channel constant (t<16 pad variant vs t>=16). Remaining work:
//   out[b,t,f] = relu( c[f] + sum_c sign(x[b,t,c])*sign(w_sc[c,f]) )
// via ballot-packed bits + xor/popc: dot = 128 - 2*popc(px^pw).
//
// R11 postmortem: tight spin recovered 6.4us (54->47.6) but ~5.9us of fixed
// sync time remains. Diagnosis: g_pcount/g_flag/g_exit share one 128B line
// (2048-block poll storm serializes the producer atomic chain), plus an extra
// block-36 polling hop, plus unthrottled poll pressure. R12: (1) each sync var
// on its own 128B line; (2) 12 chore blocks, LAST finisher does reduce+bn+flag
// inline (no dedicated waiter block); (3) ~256-cycle backoff between polls.
// (R13: resubmit, broker timeout, no data.)
// ----------------------------------------------------------------------------

__device__ int g_partial[8][128];                   // per-slab sign counts of w2
__device__ __align__(16) unsigned g_pw[128][4];     // packed sign bits of w_sc
__device__ __align__(16) float    g_add_ge[128];    // relu(bn2(S0+S1)) + 128
__device__ __align__(16) float    g_add_lt[128];    // relu(bn2(S1))    + 128
// Each sync variable on its own 128B line (no false sharing with poll storm).
__device__ __align__(128) int g_pcount[32];  // [0] used: chores done (0..12)
__device__ __align__(128) int g_flag[32];    // [0] used: constants ready
__device__ __align__(128) int g_exit[32];    // [0] used: blocks finished

// Acquire load from global (gpu scope) — poll primitive.
__device__ __forceinline__ int ld_acquire_gpu(const int* p)
{
    int v;
    asm volatile("ld.acquire.gpu.b32 %0, [%1];" : "=r"(v) : "l"(p) : "memory");
    return v;
}

// ~256-cycle dependent-ALU delay (not eliminable; no nanosleep granularity).
__device__ __forceinline__ void backoff_delay()
{
    int d = 0;
    #pragma unroll
    for (int i = 0; i < 64; ++i)
        asm volatile("add.s32 %0, %0, 1;" : "+r"(d));
}

// Row-loop body shared by both paths (R3-proven). HAS_LT = pad handling.
template <bool HAS_LT>
__device__ __forceinline__ void do_rows(const float* __restrict__ x,
                                        float* __restrict__ out,
                                        size_t row0, int lane,
                                        const uint4& pw0, const uint4& pw1,
                                        const uint4& pw2, const uint4& pw3,
                                        const float4& age, const float4& alt)
{
    #pragma unroll 4
    for (int r = 0; r < 16; ++r) {
        const size_t row = row0 + r;

        // 128 floats of this row: lane reads channels [4*lane, 4*lane+3].
        const float4 v = reinterpret_cast<const float4*>(x + row * 128)[lane];

        // Pack row sign bits: word j, bit l = sign(x[4l + j])  (>=0 -> 1).
        const unsigned px0 = __ballot_sync(0xffffffffu, v.x >= 0.f);
        const unsigned px1 = __ballot_sync(0xffffffffu, v.y >= 0.f);
        const unsigned px2 = __ballot_sync(0xffffffffu, v.z >= 0.f);
        const unsigned px3 = __ballot_sync(0xffffffffu, v.w >= 0.f);

        float a0, a1, a2, a3;
        if (HAS_LT) {
            const bool lt = ((row & 8191u) < 16u);  // conv2 causal pad region
            a0 = lt ? alt.x : age.x;
            a1 = lt ? alt.y : age.y;
            a2 = lt ? alt.z : age.z;
            a3 = lt ? alt.w : age.w;
        } else {
            a0 = age.x; a1 = age.y; a2 = age.z; a3 = age.w;
        }

        const int pc0 = __popc(px0 ^ pw0.x) + __popc(px1 ^ pw0.y)
                      + __popc(px2 ^ pw0.z) + __popc(px3 ^ pw0.w);
        const int pc1 = __popc(px0 ^ pw1.x) + __popc(px1 ^ pw1.y)
                      + __popc(px2 ^ pw1.z) + __popc(px3 ^ pw1.w);
        const int pc2 = __popc(px0 ^ pw2.x) + __popc(px1 ^ pw2.y)
                      + __popc(px2 ^ pw2.z) + __popc(px3 ^ pw2.w);
        const int pc3 = __popc(px0 ^ pw3.x) + __popc(px1 ^ pw3.y)
                      + __popc(px2 ^ pw3.z) + __popc(px3 ^ pw3.w);

        float4 o;
        o.x = fmaxf(fmaf(-2.f, (float)pc0, a0), 0.f);
        o.y = fmaxf(fmaf(-2.f, (float)pc1, a1), 0.f);
        o.z = fmaxf(fmaf(-2.f, (float)pc2, a2), 0.f);
        o.w = fmaxf(fmaf(-2.f, (float)pc3, a3), 0.f);

        reinterpret_cast<float4*>(out + row * 128)[lane] = o;
    }
}

__global__ void __launch_bounds__(256, 5) resblock_fused(
    const float* __restrict__ x,
    float* __restrict__ out,
    const float* __restrict__ w2,
    const float* __restrict__ w_sc,
    const float* __restrict__ beta2,
    const float* __restrict__ mean2,
    const float* __restrict__ var2)
{
    const int bid  = blockIdx.x;
    const int tid  = threadIdx.x;
    const int lane = tid & 31;
    const int warp = tid >> 5;

    __shared__ int sc[2][128];
    __shared__ int s_last;

    // ------------- prologue chores (blocks 0..11, all wave-1) --------------
    if (bid < 12) {
        if (bid < 8) {
            // Sign-count 32 flattened (k,c)-rows of w2 [2*128 x 128]:
            // block b owns rows b*32 .. b*32+31; k=0 -> blocks 0-3, k=1 -> 4-7.
            const int f = tid & 127;
            const int h = tid >> 7;          // 0/1: 16 rows each
            const int m0 = bid * 32 + h * 16;
            int cnt = 0;
            #pragma unroll
            for (int i = 0; i < 16; ++i)
                cnt += (w2[(m0 + i) * 128 + f] >= 0.f) ? 1 : 0;
            sc[h][f] = cnt;
            __syncthreads();
            if (tid < 128) g_partial[bid][tid] = sc[0][tid] + sc[1][tid];
        } else {
            // Pack w_sc sign word j = bid-8: bit l <-> channel c = 4*l + j.
            const int j = bid - 8;
            if (tid < 128) {
                const int f = tid;
                unsigned p = 0u;
                #pragma unroll
                for (int l = 0; l < 32; ++l)
                    if (w_sc[(4 * l + j) * 128 + f] >= 0.f) p |= (1u << l);
                g_pw[f][j] = p;
            }
        }
        __threadfence();                     // release this chore's writes
        __syncthreads();
        if (tid == 0)
            s_last = (atomicAdd(&g_pcount[0], 1) == 11) ? 1 : 0;
        __syncthreads();

        if (s_last) {
            // This block saw all 12 chores done: reduce + bn + publish.
            __threadfence();                 // acquire: order partial reads
            if (tid < 128) {
                const int f = tid;
                int t0 = 0, t1 = 0;
                #pragma unroll
                for (int s = 0; s < 4; ++s) t0 += g_partial[s][f];
                #pragma unroll
                for (int s = 4; s < 8; ++s) t1 += g_partial[s][f];
                const float S0 = 2.f * (float)t0 - 128.f;   // sum signs, k=0
                const float S1 = 2.f * (float)t1 - 128.f;   // k=1
                const float inv = rsqrtf(var2[f] + 1e-3f);
                const float cge = fmaxf(fmaf(S0 + S1 - mean2[f], inv, beta2[f]), 0.f);
                const float clt = fmaxf(fmaf(S1      - mean2[f], inv, beta2[f]), 0.f);
                g_add_ge[f] = cge + 128.f;   // fold "+128" of dot = 128 - 2*pc
                g_add_lt[f] = clt + 128.f;
                __threadfence();             // release constants
            }
            __syncthreads();
            if (tid == 0) atomicExch(&g_flag[0], 1);
        }
    }

    // ---------------- worker path (all 2048 blocks) ------------------------
    const int f0 = 4 * lane;
    const size_t row0 = (size_t)bid * 128 + (size_t)warp * 16;

    // Acquire-poll with ~256-cycle backoff: fast single-poll path for blocks
    // arriving after the flag; bounded L2 pressure for wave-1 waiters.
    if (tid == 0) {
        while (ld_acquire_gpu(&g_flag[0]) == 0) backoff_delay();
    }
    __syncthreads();

    // Row-invariant weights/constants into registers. Never touched by this
    // block pre-flag -> no stale L1 copies; acquire + syncthreads orders them.
    const uint4 pw0 = *reinterpret_cast<const uint4*>(g_pw[f0 + 0]);
    const uint4 pw1 = *reinterpret_cast<const uint4*>(g_pw[f0 + 1]);
    const uint4 pw2 = *reinterpret_cast<const uint4*>(g_pw[f0 + 2]);
    const uint4 pw3 = *reinterpret_cast<const uint4*>(g_pw[f0 + 3]);
    const float4 age = *reinterpret_cast<const float4*>(&g_add_ge[f0]);
    const float4 alt = *reinterpret_cast<const float4*>(&g_add_lt[f0]);

    // Rows with t<16 exist only in warp 0 of every 64th block (8192/128=64).
    if (warp == 0 && (bid & 63) == 0) {
        do_rows<true >(x, out, row0, lane, pw0, pw1, pw2, pw3, age, alt);
    } else {
        do_rows<false>(x, out, row0, lane, pw0, pw1, pw2, pw3, age, alt);
    }

    // ---------------- reset protocol (deterministic graph replays) ---------
    if (tid == 0) {
        const int n = atomicAdd(&g_exit[0], 1);
        if (n == (int)gridDim.x - 1) {       // last block: restore sync state
            g_pcount[0] = 0;
            g_flag[0]   = 0;
            __threadfence();
            g_exit[0]   = 0;
        }
    }
}

extern "C" void kernel_launch(void* const* d_in, const int* in_sizes, int n_in,
                              void* d_out, int out_size)
{
    // metadata order: x, w1, w2, w_sc, beta1, mean1, var1, beta2, mean2, var2
    const float* x     = (const float*)d_in[0];
    const float* w2    = (const float*)d_in[2];
    const float* w_sc  = (const float*)d_in[3];
    const float* beta2 = (const float*)d_in[7];
    const float* mean2 = (const float*)d_in[8];
    const float* var2  = (const float*)d_in[9];
    float* out = (float*)d_out;

    // 262144 rows / 128 rows per block = 2048 blocks, one launch total.
    resblock_fused<<<2048, 256>>>(x, out, w2, w_sc, beta2, mean2, var2);
}